// round 1
// baseline (speedup 1.0000x reference)
#include <cuda_runtime.h>
#include <math.h>

#define Bq 64
#define Sq 128
#define Eq 512
#define Hq 1024
#define Vq 50257
#define KIq (Eq + Hq)   /* 1536 */
#define G4q (4 * Hq)    /* 4096 */
#define SBq (Sq * Bq)   /* 8192 */

// ---------------- scratch (static device globals; no runtime allocation) ----
__device__ float g_hW[Bq * Hq];
__device__ float g_T[SBq * Hq];        // 33.5 MB energy pre-activation
__device__ float g_score[Bq * Sq];
__device__ float g_ctx[Bq * Hq];
__device__ float g_x[Bq * KIq];
__device__ float g_gates[Bq * G4q];

// ---------------- generic tiled SGEMM: C[M,N] = A[M,K] @ B[N,K]^T (+bias)(+=C)
// Requirements: M % BM == 0, K % BK == 0. N may be ragged (guarded).
template <int BM, int BN, int BK, int TM, int TN>
__global__ void __launch_bounds__((BM / TM) * (BN / TN))
sgemm_nt(const float* __restrict__ A, const float* __restrict__ Bm,
         float* __restrict__ C, int M, int N, int K,
         const float* __restrict__ bias, int accum)
{
    constexpr int TX = BN / TN;
    constexpr int TY = BM / TM;
    constexpr int KF4 = BK / 4;
    __shared__ float As[BK][BM];
    __shared__ float Bs[BK][BN];

    const int tid = threadIdx.x;
    const int tx = tid % TX;
    const int ty = tid / TX;
    const int m0 = blockIdx.y * BM;
    const int n0 = blockIdx.x * BN;

    // each thread loads exactly one float4 of each tile per K-step
    const int lrow = tid / KF4;
    const int lk = (tid % KF4) * 4;

    float acc[TM][TN];
#pragma unroll
    for (int i = 0; i < TM; i++)
#pragma unroll
        for (int j = 0; j < TN; j++) acc[i][j] = 0.f;

    for (int k0 = 0; k0 < K; k0 += BK) {
        {
            float4 v = *reinterpret_cast<const float4*>(
                A + (size_t)(m0 + lrow) * K + k0 + lk);
            As[lk + 0][lrow] = v.x; As[lk + 1][lrow] = v.y;
            As[lk + 2][lrow] = v.z; As[lk + 3][lrow] = v.w;
        }
        {
            float4 v = make_float4(0.f, 0.f, 0.f, 0.f);
            if (n0 + lrow < N)
                v = *reinterpret_cast<const float4*>(
                    Bm + (size_t)(n0 + lrow) * K + k0 + lk);
            Bs[lk + 0][lrow] = v.x; Bs[lk + 1][lrow] = v.y;
            Bs[lk + 2][lrow] = v.z; Bs[lk + 3][lrow] = v.w;
        }
        __syncthreads();

#pragma unroll
        for (int kk = 0; kk < BK; kk++) {
            float a[TM], b[TN];
#pragma unroll
            for (int i = 0; i < TM / 4; i++)
                *reinterpret_cast<float4*>(&a[4 * i]) =
                    *reinterpret_cast<const float4*>(&As[kk][ty * TM + 4 * i]);
#pragma unroll
            for (int j = 0; j < TN / 4; j++)
                *reinterpret_cast<float4*>(&b[4 * j]) =
                    *reinterpret_cast<const float4*>(&Bs[kk][tx * TN + 4 * j]);
#pragma unroll
            for (int i = 0; i < TM; i++)
#pragma unroll
                for (int j = 0; j < TN; j++)
                    acc[i][j] = fmaf(a[i], b[j], acc[i][j]);
        }
        __syncthreads();
    }

#pragma unroll
    for (int i = 0; i < TM; i++) {
        int gm = m0 + ty * TM + i;
#pragma unroll
        for (int j = 0; j < TN; j++) {
            int gn = n0 + tx * TN + j;
            if (gn < N) {
                float r = acc[i][j];
                if (bias) r += bias[gn];
                size_t off = (size_t)gm * N + gn;
                if (accum) r += C[off];
                C[off] = r;
            }
        }
    }
}

// score[b][s] = sum_h v[h] * tanh(T[s*B+b][h] + hW[b][h])   (Ub folded into T)
__global__ void score_kernel(const float* __restrict__ v)
{
    int r = blockIdx.x * 8 + (threadIdx.x >> 5);
    int lane = threadIdx.x & 31;
    if (r >= SBq) return;
    int s = r / Bq, b = r % Bq;
    const float* Tr = g_T + (size_t)r * Hq;
    const float* hWb = g_hW + b * Hq;
    float sum = 0.f;
    for (int h = lane; h < Hq; h += 32)
        sum += v[h] * tanhf(Tr[h] + hWb[h]);
#pragma unroll
    for (int o = 16; o > 0; o >>= 1) sum += __shfl_xor_sync(~0u, sum, o);
    if (lane == 0) g_score[b * Sq + s] = sum;
}

// softmax over S per batch row; writes directly into the attn_w output region
__global__ void softmax_kernel(float* __restrict__ attn_out)
{
    __shared__ float sm[Sq];
    int b = blockIdx.x, t = threadIdx.x;
    float x = g_score[b * Sq + t];
    sm[t] = x; __syncthreads();
    for (int o = 64; o > 0; o >>= 1) {
        if (t < o) sm[t] = fmaxf(sm[t], sm[t + o]);
        __syncthreads();
    }
    float m = sm[0];
    __syncthreads();
    float e = expf(x - m);
    sm[t] = e; __syncthreads();
    for (int o = 64; o > 0; o >>= 1) {
        if (t < o) sm[t] += sm[t + o];
        __syncthreads();
    }
    float inv = 1.f / sm[0];
    attn_out[b * Sq + t] = e * inv;
}

// context[b][h] = sum_s attn[b][s] * enc[s][b][h]
__global__ void context_kernel(const float* __restrict__ attn,
                               const float* __restrict__ enc)
{
    __shared__ float aw[Sq];
    int idx = blockIdx.x * 256 + threadIdx.x;   // [0, B*H)
    int b = idx >> 10;                           // 256 | 1024 -> b const/block
    int h = idx & (Hq - 1);
    if (threadIdx.x < Sq) aw[threadIdx.x] = attn[b * Sq + threadIdx.x];
    __syncthreads();
    float acc = 0.f;
#pragma unroll 4
    for (int s = 0; s < Sq; s++)
        acc = fmaf(aw[s], enc[((size_t)s * Bq + b) * Hq + h], acc);
    g_ctx[idx] = acc;
}

// x[b] = [ emb[seq[b]] (E) ; context[b] (H) ]
__global__ void xbuild_kernel(const int* __restrict__ seq,
                              const float* __restrict__ emb)
{
    int idx = blockIdx.x * 256 + threadIdx.x;   // [0, B*KI)
    int b = idx / KIq;
    int j = idx - b * KIq;
    float val;
    if (j < Eq) val = emb[(size_t)seq[b] * Eq + j];
    else        val = g_ctx[b * Hq + (j - Eq)];
    g_x[idx] = val;
}

__device__ __forceinline__ float sigf(float x) { return 1.f / (1.f + expf(-x)); }

// LSTM pointwise: gates order i, f, g, o
__global__ void lstm_kernel(const float* __restrict__ c0,
                            float* __restrict__ h_new,
                            float* __restrict__ c_new)
{
    int idx = blockIdx.x * 256 + threadIdx.x;   // [0, B*H)
    int b = idx >> 10;
    int h = idx & (Hq - 1);
    const float* g = g_gates + ((size_t)b << 12);
    float vi = g[h];
    float vf = g[Hq + h];
    float vg = g[2 * Hq + h];
    float vo = g[3 * Hq + h];
    float c = sigf(vf) * c0[idx] + sigf(vi) * tanhf(vg);
    c_new[idx] = c;
    h_new[idx] = sigf(vo) * tanhf(c);
}

__device__ __forceinline__ float blk_red_max(float v, float* red)
{
    int t = threadIdx.x;
#pragma unroll
    for (int o = 16; o > 0; o >>= 1) v = fmaxf(v, __shfl_xor_sync(~0u, v, o));
    if ((t & 31) == 0) red[t >> 5] = v;
    __syncthreads();
    if (t < 32) {
        v = red[t];
#pragma unroll
        for (int o = 16; o > 0; o >>= 1) v = fmaxf(v, __shfl_xor_sync(~0u, v, o));
        if (t == 0) red[0] = v;
    }
    __syncthreads();
    float r = red[0];
    __syncthreads();
    return r;
}

__device__ __forceinline__ float blk_red_sum(float v, float* red)
{
    int t = threadIdx.x;
#pragma unroll
    for (int o = 16; o > 0; o >>= 1) v += __shfl_xor_sync(~0u, v, o);
    if ((t & 31) == 0) red[t >> 5] = v;
    __syncthreads();
    if (t < 32) {
        v = red[t];
#pragma unroll
        for (int o = 16; o > 0; o >>= 1) v += __shfl_xor_sync(~0u, v, o);
        if (t == 0) red[0] = v;
    }
    __syncthreads();
    float r = red[0];
    __syncthreads();
    return r;
}

// in-place log_softmax over V per batch row (blockDim = 1024, 32 warps)
__global__ void logsoftmax_kernel(float* __restrict__ out)
{
    __shared__ float red[32];
    int b = blockIdx.x;
    float* row = out + (size_t)b * Vq;
    int t = threadIdx.x;

    float m = -1e30f;
    for (int j = t; j < Vq; j += 1024) m = fmaxf(m, row[j]);
    m = blk_red_max(m, red);

    float s = 0.f;
    for (int j = t; j < Vq; j += 1024) s += expf(row[j] - m);
    s = blk_red_sum(s, red);

    float lse = m + logf(s);
    for (int j = t; j < Vq; j += 1024) row[j] -= lse;
}

// ---------------------------------------------------------------------------
extern "C" void kernel_launch(void* const* d_in, const int* in_sizes, int n_in,
                              void* d_out, int out_size)
{
    const int*   seq     = (const int*)d_in[0];
    const float* h0      = (const float*)d_in[1];
    const float* c0      = (const float*)d_in[2];
    const float* enc     = (const float*)d_in[3];
    const float* emb     = (const float*)d_in[4];
    const float* W_ih    = (const float*)d_in[5];
    const float* W_hh    = (const float*)d_in[6];
    const float* b_ih    = (const float*)d_in[7];
    const float* b_hh    = (const float*)d_in[8];
    const float* attn_W  = (const float*)d_in[9];
    const float* attn_Wb = (const float*)d_in[10];
    const float* attn_U  = (const float*)d_in[11];
    const float* attn_Ub = (const float*)d_in[12];
    const float* attn_v  = (const float*)d_in[13];
    const float* out_W   = (const float*)d_in[14];
    const float* out_b   = (const float*)d_in[15];

    float* out      = (float*)d_out;
    float* o_logits = out;                          // [B, V]
    float* o_h      = out + (size_t)Bq * Vq;        // [1, B, H]
    float* o_c      = o_h + Bq * Hq;                // [1, B, H]
    float* o_attn   = o_c + Bq * Hq;                // [B, 1, S]

    float *hW, *T, *x, *gates;
    cudaGetSymbolAddress((void**)&hW,    g_hW);
    cudaGetSymbolAddress((void**)&T,     g_T);
    cudaGetSymbolAddress((void**)&x,     g_x);
    cudaGetSymbolAddress((void**)&gates, g_gates);

    // 1) hW = h0 @ attn_W^T + attn_Wb            [64, 1024]
    sgemm_nt<64, 64, 16, 4, 4><<<dim3(Hq / 64, Bq / 64), 256>>>(
        h0, attn_W, hW, Bq, Hq, Hq, attn_Wb, 0);

    // 2) T = enc @ attn_U^T + attn_Ub            [8192, 1024]  (dominant GEMM)
    sgemm_nt<128, 128, 8, 8, 8><<<dim3(Hq / 128, SBq / 128), 256>>>(
        enc, attn_U, T, SBq, Hq, Hq, attn_Ub, 0);

    // 3) score = v . tanh(T + hW)                [64, 128]
    score_kernel<<<SBq / 8, 256>>>(attn_v);

    // 4) attn = softmax(score) -> output region
    softmax_kernel<<<Bq, Sq>>>(o_attn);

    // 5) context = attn @ enc                    [64, 1024]
    context_kernel<<<Bq * Hq / 256, 256>>>(o_attn, enc);

    // 6) x = [emb[seq] ; context]                [64, 1536]
    xbuild_kernel<<<Bq * KIq / 256, 256>>>(seq, emb);

    // 7) gates  = x @ W_ih^T + b_ih              [64, 4096]
    sgemm_nt<64, 64, 16, 4, 4><<<dim3(G4q / 64, 1), 256>>>(
        x, W_ih, gates, Bq, G4q, KIq, b_ih, 0);

    // 8) gates += h0 @ W_hh^T + b_hh
    sgemm_nt<64, 64, 16, 4, 4><<<dim3(G4q / 64, 1), 256>>>(
        h0, W_hh, gates, Bq, G4q, Hq, b_hh, 1);

    // 9) LSTM pointwise -> h_new, c_new in output
    lstm_kernel<<<Bq * Hq / 256, 256>>>(c0, o_h, o_c);

    // 10) logits = h_new @ out_W^T + out_b       [64, 50257]
    sgemm_nt<64, 64, 16, 4, 4><<<dim3((Vq + 63) / 64, 1), 256>>>(
        o_h, out_W, o_logits, Bq, Vq, Hq, out_b, 0);

    // 11) in-place log_softmax over V
    logsoftmax_kernel<<<Bq, 1024>>>(o_logits);
}

// round 3
// speedup vs baseline: 1.0821x; 1.0821x over previous
#include <cuda_runtime.h>
#include <math.h>

#define Bq 64
#define Sq 128
#define Eq 512
#define Hq 1024
#define Vq 50257
#define KIq (Eq + Hq)   /* 1536 */
#define G4q (4 * Hq)    /* 4096 */
#define SBq (Sq * Bq)   /* 8192 */

// ---------------- scratch (static device globals; no runtime allocation) ----
__device__ float g_hW[Bq * Hq];
__device__ float g_T[SBq * Hq];        // 33.5 MB energy pre-activation
__device__ float g_score[Bq * Sq];
__device__ float g_ctx[Bq * Hq];
__device__ float g_x[Bq * KIq];
__device__ float g_gates[Bq * G4q];

// ---------------- tf32 helpers ---------------------------------------------
__device__ __forceinline__ unsigned f2tf32(float x)
{
    unsigned r;
    asm("cvt.rna.tf32.f32 %0, %1;" : "=r"(r) : "f"(x));
    return r;
}

__device__ __forceinline__ void split_tf32(float x, unsigned& hi, unsigned& lo)
{
    hi = f2tf32(x);
    lo = f2tf32(x - __uint_as_float(hi));
}

__device__ __forceinline__ void mma_tf32(float c[4], const unsigned a[4],
                                         const unsigned b[2])
{
    asm volatile(
        "mma.sync.aligned.m16n8k8.row.col.f32.tf32.tf32.f32 "
        "{%0,%1,%2,%3}, {%4,%5,%6,%7}, {%8,%9}, {%0,%1,%2,%3};"
        : "+f"(c[0]), "+f"(c[1]), "+f"(c[2]), "+f"(c[3])
        : "r"(a[0]), "r"(a[1]), "r"(a[2]), "r"(a[3]), "r"(b[0]), "r"(b[1]));
}

// ======================= single-pass tf32 GEMM ==============================
// C[M,N] = A[M,K] @ B[N,K]^T (+bias). M%BM==0, K%BK==0, N ragged.
template <int BM, int BN, int BK, int WM, int WN>
__global__ void __launch_bounds__(256)
mma_gemm_nt(const float* __restrict__ A, const float* __restrict__ Bm,
            float* __restrict__ C, int M, int N, int K,
            const float* __restrict__ bias)
{
    constexpr int MI = WM / 16;
    constexpr int NI = WN / 8;
    constexpr int KP = BK + 4;
    constexpr int F4R = BK / 4;
    constexpr int RPP = 256 / F4R;

    __shared__ unsigned As[BM][KP];
    __shared__ unsigned Bs[BN][KP];

    const int tid = threadIdx.x;
    const int lane = tid & 31;
    const int w = tid >> 5;
    const int warp_m = (w % (BM / WM)) * WM;
    const int warp_n = (w / (BM / WM)) * WN;
    const int m0 = blockIdx.y * BM;
    const int n0 = blockIdx.x * BN;
    const int lrow = tid / F4R;
    const int lk4 = (tid % F4R) * 4;

    float acc[MI][NI][4];
#pragma unroll
    for (int i = 0; i < MI; i++)
#pragma unroll
        for (int j = 0; j < NI; j++)
#pragma unroll
            for (int q = 0; q < 4; q++) acc[i][j][q] = 0.f;

    for (int k0 = 0; k0 < K; k0 += BK) {
#pragma unroll
        for (int r = lrow; r < BM; r += RPP) {
            float4 v = *reinterpret_cast<const float4*>(
                A + (size_t)(m0 + r) * K + k0 + lk4);
            uint4 u;
            u.x = f2tf32(v.x); u.y = f2tf32(v.y);
            u.z = f2tf32(v.z); u.w = f2tf32(v.w);
            *reinterpret_cast<uint4*>(&As[r][lk4]) = u;
        }
#pragma unroll
        for (int r = lrow; r < BN; r += RPP) {
            float4 v = make_float4(0.f, 0.f, 0.f, 0.f);
            if (n0 + r < N)
                v = *reinterpret_cast<const float4*>(
                    Bm + (size_t)(n0 + r) * K + k0 + lk4);
            uint4 u;
            u.x = f2tf32(v.x); u.y = f2tf32(v.y);
            u.z = f2tf32(v.z); u.w = f2tf32(v.w);
            *reinterpret_cast<uint4*>(&Bs[r][lk4]) = u;
        }
        __syncthreads();

#pragma unroll
        for (int kk = 0; kk < BK; kk += 8) {
            unsigned af[MI][4], bf[NI][2];
#pragma unroll
            for (int i = 0; i < MI; i++) {
                int r = warp_m + i * 16 + (lane >> 2);
                int cb = kk + (lane & 3);
                af[i][0] = As[r][cb];     af[i][1] = As[r + 8][cb];
                af[i][2] = As[r][cb + 4]; af[i][3] = As[r + 8][cb + 4];
            }
#pragma unroll
            for (int j = 0; j < NI; j++) {
                int r = warp_n + j * 8 + (lane >> 2);
                int cb = kk + (lane & 3);
                bf[j][0] = Bs[r][cb]; bf[j][1] = Bs[r][cb + 4];
            }
#pragma unroll
            for (int i = 0; i < MI; i++)
#pragma unroll
                for (int j = 0; j < NI; j++)
                    mma_tf32(acc[i][j], af[i], bf[j]);
        }
        __syncthreads();
    }

#pragma unroll
    for (int i = 0; i < MI; i++)
#pragma unroll
        for (int j = 0; j < NI; j++) {
            int row = m0 + warp_m + i * 16 + (lane >> 2);
            int col = n0 + warp_n + j * 8 + 2 * (lane & 3);
#pragma unroll
            for (int q = 0; q < 4; q++) {
                int gr = row + (q >> 1) * 8;
                int gc = col + (q & 1);
                if (gc < N) {
                    float r = acc[i][j][q];
                    if (bias) r += bias[gc];
                    C[(size_t)gr * N + gc] = r;
                }
            }
        }
}

// ======================= 3xTF32 (fp32-accurate) GEMM ========================
// C = A @ B^T (+bias) (+=C if accum). Ah*Bh + Ah*Bl + Al*Bh.
template <int BM, int BN, int BK, int WM, int WN>
__global__ void __launch_bounds__(256)
mma3_gemm_nt(const float* __restrict__ A, const float* __restrict__ Bm,
             float* __restrict__ C, int M, int N, int K,
             const float* __restrict__ bias, int accum)
{
    constexpr int MI = WM / 16;
    constexpr int NI = WN / 8;
    constexpr int KP = BK + 4;
    constexpr int F4R = BK / 4;
    constexpr int RPP = 256 / F4R;

    __shared__ unsigned Ah[BM][KP], Al[BM][KP];
    __shared__ unsigned Bh[BN][KP], Bl[BN][KP];

    const int tid = threadIdx.x;
    const int lane = tid & 31;
    const int w = tid >> 5;
    const int warp_m = (w % (BM / WM)) * WM;
    const int warp_n = (w / (BM / WM)) * WN;
    const int m0 = blockIdx.y * BM;
    const int n0 = blockIdx.x * BN;
    const int lrow = tid / F4R;
    const int lk4 = (tid % F4R) * 4;

    float acc[MI][NI][4];
#pragma unroll
    for (int i = 0; i < MI; i++)
#pragma unroll
        for (int j = 0; j < NI; j++)
#pragma unroll
            for (int q = 0; q < 4; q++) acc[i][j][q] = 0.f;

    for (int k0 = 0; k0 < K; k0 += BK) {
#pragma unroll
        for (int r = lrow; r < BM; r += RPP) {
            float4 v = *reinterpret_cast<const float4*>(
                A + (size_t)(m0 + r) * K + k0 + lk4);
            uint4 uh, ul;
            split_tf32(v.x, uh.x, ul.x); split_tf32(v.y, uh.y, ul.y);
            split_tf32(v.z, uh.z, ul.z); split_tf32(v.w, uh.w, ul.w);
            *reinterpret_cast<uint4*>(&Ah[r][lk4]) = uh;
            *reinterpret_cast<uint4*>(&Al[r][lk4]) = ul;
        }
#pragma unroll
        for (int r = lrow; r < BN; r += RPP) {
            float4 v = make_float4(0.f, 0.f, 0.f, 0.f);
            if (n0 + r < N)
                v = *reinterpret_cast<const float4*>(
                    Bm + (size_t)(n0 + r) * K + k0 + lk4);
            uint4 uh, ul;
            split_tf32(v.x, uh.x, ul.x); split_tf32(v.y, uh.y, ul.y);
            split_tf32(v.z, uh.z, ul.z); split_tf32(v.w, uh.w, ul.w);
            *reinterpret_cast<uint4*>(&Bh[r][lk4]) = uh;
            *reinterpret_cast<uint4*>(&Bl[r][lk4]) = ul;
        }
        __syncthreads();

#pragma unroll
        for (int kk = 0; kk < BK; kk += 8) {
            unsigned ah[MI][4], al[MI][4], bh[NI][2], bl[NI][2];
#pragma unroll
            for (int i = 0; i < MI; i++) {
                int r = warp_m + i * 16 + (lane >> 2);
                int cb = kk + (lane & 3);
                ah[i][0] = Ah[r][cb];     ah[i][1] = Ah[r + 8][cb];
                ah[i][2] = Ah[r][cb + 4]; ah[i][3] = Ah[r + 8][cb + 4];
                al[i][0] = Al[r][cb];     al[i][1] = Al[r + 8][cb];
                al[i][2] = Al[r][cb + 4]; al[i][3] = Al[r + 8][cb + 4];
            }
#pragma unroll
            for (int j = 0; j < NI; j++) {
                int r = warp_n + j * 8 + (lane >> 2);
                int cb = kk + (lane & 3);
                bh[j][0] = Bh[r][cb]; bh[j][1] = Bh[r][cb + 4];
                bl[j][0] = Bl[r][cb]; bl[j][1] = Bl[r][cb + 4];
            }
#pragma unroll
            for (int i = 0; i < MI; i++)
#pragma unroll
                for (int j = 0; j < NI; j++) {
                    mma_tf32(acc[i][j], ah[i], bl[j]);
                    mma_tf32(acc[i][j], al[i], bh[j]);
                    mma_tf32(acc[i][j], ah[i], bh[j]);
                }
        }
        __syncthreads();
    }

#pragma unroll
    for (int i = 0; i < MI; i++)
#pragma unroll
        for (int j = 0; j < NI; j++) {
            int row = m0 + warp_m + i * 16 + (lane >> 2);
            int col = n0 + warp_n + j * 8 + 2 * (lane & 3);
#pragma unroll
            for (int q = 0; q < 4; q++) {
                int gr = row + (q >> 1) * 8;
                int gc = col + (q & 1);
                if (gc < N) {
                    float r = acc[i][j][q];
                    if (bias) r += bias[gc];
                    size_t off = (size_t)gr * N + gc;
                    if (accum) r += C[off];
                    C[off] = r;
                }
            }
        }
}

// score[b][s] = sum_h v[h] * tanh(T[s*B+b][h] + hW[b][h])
__global__ void score_kernel(const float* __restrict__ v)
{
    int r = blockIdx.x * 8 + (threadIdx.x >> 5);
    int lane = threadIdx.x & 31;
    if (r >= SBq) return;
    int s = r / Bq, b = r % Bq;
    const float* Tr = g_T + (size_t)r * Hq;
    const float* hWb = g_hW + b * Hq;
    float sum = 0.f;
    for (int h = lane; h < Hq; h += 32)
        sum += v[h] * tanhf(Tr[h] + hWb[h]);
#pragma unroll
    for (int o = 16; o > 0; o >>= 1) sum += __shfl_xor_sync(~0u, sum, o);
    if (lane == 0) g_score[b * Sq + s] = sum;
}

// softmax over S per batch row; writes into the attn_w output region
__global__ void softmax_kernel(float* __restrict__ attn_out)
{
    __shared__ float sm[Sq];
    int b = blockIdx.x, t = threadIdx.x;
    float x = g_score[b * Sq + t];
    sm[t] = x; __syncthreads();
    for (int o = 64; o > 0; o >>= 1) {
        if (t < o) sm[t] = fmaxf(sm[t], sm[t + o]);
        __syncthreads();
    }
    float m = sm[0];
    __syncthreads();
    float e = expf(x - m);
    sm[t] = e; __syncthreads();
    for (int o = 64; o > 0; o >>= 1) {
        if (t < o) sm[t] += sm[t + o];
        __syncthreads();
    }
    float inv = 1.f / sm[0];
    attn_out[b * Sq + t] = e * inv;
}

// context[b][h] = sum_s attn[b][s] * enc[s][b][h]
__global__ void context_kernel(const float* __restrict__ attn,
                               const float* __restrict__ enc)
{
    __shared__ float aw[Sq];
    int idx = blockIdx.x * 256 + threadIdx.x;
    int b = idx >> 10;
    int h = idx & (Hq - 1);
    if (threadIdx.x < Sq) aw[threadIdx.x] = attn[b * Sq + threadIdx.x];
    __syncthreads();
    float acc = 0.f;
#pragma unroll 4
    for (int s = 0; s < Sq; s++)
        acc = fmaf(aw[s], enc[((size_t)s * Bq + b) * Hq + h], acc);
    g_ctx[idx] = acc;
}

// x[b] = [ emb[seq[b]] (E) ; context[b] (H) ]
__global__ void xbuild_kernel(const int* __restrict__ seq,
                              const float* __restrict__ emb)
{
    int idx = blockIdx.x * 256 + threadIdx.x;
    int b = idx / KIq;
    int j = idx - b * KIq;
    float val;
    if (j < Eq) val = emb[(size_t)seq[b] * Eq + j];
    else        val = g_ctx[b * Hq + (j - Eq)];
    g_x[idx] = val;
}

__device__ __forceinline__ float sigf(float x) { return 1.f / (1.f + expf(-x)); }

// LSTM pointwise: gates order i, f, g, o
__global__ void lstm_kernel(const float* __restrict__ c0,
                            float* __restrict__ h_new,
                            float* __restrict__ c_new)
{
    int idx = blockIdx.x * 256 + threadIdx.x;
    int b = idx >> 10;
    int h = idx & (Hq - 1);
    const float* g = g_gates + ((size_t)b << 12);
    float vi = g[h];
    float vf = g[Hq + h];
    float vg = g[2 * Hq + h];
    float vo = g[3 * Hq + h];
    float c = sigf(vf) * c0[idx] + sigf(vi) * tanhf(vg);
    c_new[idx] = c;
    h_new[idx] = sigf(vo) * tanhf(c);
}

__device__ __forceinline__ float blk_red_max(float v, float* red)
{
    int t = threadIdx.x;
#pragma unroll
    for (int o = 16; o > 0; o >>= 1) v = fmaxf(v, __shfl_xor_sync(~0u, v, o));
    if ((t & 31) == 0) red[t >> 5] = v;
    __syncthreads();
    if (t < 32) {
        v = red[t];
#pragma unroll
        for (int o = 16; o > 0; o >>= 1) v = fmaxf(v, __shfl_xor_sync(~0u, v, o));
        if (t == 0) red[0] = v;
    }
    __syncthreads();
    float r = red[0];
    __syncthreads();
    return r;
}

__device__ __forceinline__ float blk_red_sum(float v, float* red)
{
    int t = threadIdx.x;
#pragma unroll
    for (int o = 16; o > 0; o >>= 1) v += __shfl_xor_sync(~0u, v, o);
    if ((t & 31) == 0) red[t >> 5] = v;
    __syncthreads();
    if (t < 32) {
        v = red[t];
#pragma unroll
        for (int o = 16; o > 0; o >>= 1) v += __shfl_xor_sync(~0u, v, o);
        if (t == 0) red[0] = v;
    }
    __syncthreads();
    float r = red[0];
    __syncthreads();
    return r;
}

// in-place log_softmax over V per batch row
__global__ void logsoftmax_kernel(float* __restrict__ out)
{
    __shared__ float red[32];
    int b = blockIdx.x;
    float* row = out + (size_t)b * Vq;
    int t = threadIdx.x;

    float m = -1e30f;
    for (int j = t; j < Vq; j += 1024) m = fmaxf(m, row[j]);
    m = blk_red_max(m, red);

    float s = 0.f;
    for (int j = t; j < Vq; j += 1024) s += expf(row[j] - m);
    s = blk_red_sum(s, red);

    float lse = m + logf(s);
    for (int j = t; j < Vq; j += 1024) row[j] -= lse;
}

// ---------------------------------------------------------------------------
extern "C" void kernel_launch(void* const* d_in, const int* in_sizes, int n_in,
                              void* d_out, int out_size)
{
    const int*   seq     = (const int*)d_in[0];
    const float* h0      = (const float*)d_in[1];
    const float* c0      = (const float*)d_in[2];
    const float* enc     = (const float*)d_in[3];
    const float* emb     = (const float*)d_in[4];
    const float* W_ih    = (const float*)d_in[5];
    const float* W_hh    = (const float*)d_in[6];
    const float* b_ih    = (const float*)d_in[7];
    const float* b_hh    = (const float*)d_in[8];
    const float* attn_W  = (const float*)d_in[9];
    const float* attn_Wb = (const float*)d_in[10];
    const float* attn_U  = (const float*)d_in[11];
    const float* attn_Ub = (const float*)d_in[12];
    const float* attn_v  = (const float*)d_in[13];
    const float* out_W   = (const float*)d_in[14];
    const float* out_b   = (const float*)d_in[15];

    float* out      = (float*)d_out;
    float* o_logits = out;                          // [B, V]
    float* o_h      = out + (size_t)Bq * Vq;        // [1, B, H]
    float* o_c      = o_h + Bq * Hq;                // [1, B, H]
    float* o_attn   = o_c + Bq * Hq;                // [B, 1, S]

    float *hW, *T, *x, *gates;
    cudaGetSymbolAddress((void**)&hW,    g_hW);
    cudaGetSymbolAddress((void**)&T,     g_T);
    cudaGetSymbolAddress((void**)&x,     g_x);
    cudaGetSymbolAddress((void**)&gates, g_gates);

    // 1) hW = h0 @ attn_W^T + attn_Wb            [64, 1024]   (3xTF32)
    mma3_gemm_nt<64, 128, 16, 32, 32><<<dim3(Hq / 128, 1), 256>>>(
        h0, attn_W, hW, Bq, Hq, Hq, attn_Wb, 0);

    // 2) T = enc @ attn_U^T + attn_Ub            [8192, 1024] (3xTF32)
    mma3_gemm_nt<128, 128, 16, 64, 32><<<dim3(Hq / 128, SBq / 128), 256>>>(
        enc, attn_U, T, SBq, Hq, Hq, attn_Ub, 0);

    // 3) score = v . tanh(T + hW)                [64, 128]
    score_kernel<<<SBq / 8, 256>>>(attn_v);

    // 4) attn = softmax(score) -> output region
    softmax_kernel<<<Bq, Sq>>>(o_attn);

    // 5) context = attn @ enc                    [64, 1024]
    context_kernel<<<Bq * Hq / 256, 256>>>(o_attn, enc);

    // 6) x = [emb[seq] ; context]                [64, 1536]
    xbuild_kernel<<<Bq * KIq / 256, 256>>>(seq, emb);

    // 7) gates  = x @ W_ih^T + b_ih              [64, 4096]   (3xTF32)
    mma3_gemm_nt<64, 128, 16, 32, 32><<<dim3(G4q / 128, 1), 256>>>(
        x, W_ih, gates, Bq, G4q, KIq, b_ih, 0);

    // 8) gates += h0 @ W_hh^T + b_hh                          (3xTF32)
    mma3_gemm_nt<64, 128, 16, 32, 32><<<dim3(G4q / 128, 1), 256>>>(
        h0, W_hh, gates, Bq, G4q, Hq, b_hh, 1);

    // 9) LSTM pointwise -> h_new, c_new in output
    lstm_kernel<<<Bq * Hq / 256, 256>>>(c0, o_h, o_c);

    // 10) logits = h_new @ out_W^T + out_b       [64, 50257]  (single tf32)
    mma_gemm_nt<64, 128, 32, 32, 32><<<dim3((Vq + 127) / 128, 1), 256>>>(
        o_h, out_W, o_logits, Bq, Vq, Hq, out_b);

    // 11) in-place log_softmax over V
    logsoftmax_kernel<<<Bq, 1024>>>(o_logits);
}